// round 1
// baseline (speedup 1.0000x reference)
#include <cuda_runtime.h>
#include <cstdint>
#include <cstddef>

// Problem dims
#define BB 256
#define TT 512
#define II 128
#define HH 256
#define GG 768   // 3*H

// ---------------------------------------------------------------------------
// Scratch: precomputed input projections xg[b*T+t][768]  (402 MB, static)
// ---------------------------------------------------------------------------
__device__ float g_xg[(size_t)BB * TT * GG];

// ---------------------------------------------------------------------------
// Phase 1:  xg = x @ W_ih^T + b_ih      (M=131072, N=768, K=128)
// 64x64 tiles, 256 threads, 4x4 register tile, k-major smem staging.
// ---------------------------------------------------------------------------
__global__ __launch_bounds__(256, 1) void xg_gemm_kernel(
    const float* __restrict__ x,
    const float* __restrict__ Wih,
    const float* __restrict__ bih)
{
    __shared__ float xs[64][68];
    __shared__ float ws[64][68];
    const int tid = threadIdx.x;
    const int bm = blockIdx.x;
    const int bn = blockIdx.y;
    const float* xr = x   + (size_t)bm * 64 * II;
    const float* wr = Wih + (size_t)bn * 64 * II;
    const int r0 = (tid >> 4) << 2;   // bt-rows 0..60
    const int c0 = (tid & 15) << 2;   // cols    0..60

    float acc[4][4];
#pragma unroll
    for (int i = 0; i < 4; ++i)
#pragma unroll
        for (int j = 0; j < 4; ++j) acc[i][j] = 0.f;

    for (int kt = 0; kt < 2; ++kt) {
        // stage 64 rows x 64 k of x and W (transposed to k-major)
#pragma unroll
        for (int l = 0; l < 4; ++l) {
            int f   = l * 256 + tid;
            int row = f >> 4;
            int kq  = f & 15;
            float4 v = *(const float4*)(xr + (size_t)row * II + kt * 64 + kq * 4);
            xs[kq * 4 + 0][row] = v.x; xs[kq * 4 + 1][row] = v.y;
            xs[kq * 4 + 2][row] = v.z; xs[kq * 4 + 3][row] = v.w;
            float4 w = *(const float4*)(wr + (size_t)row * II + kt * 64 + kq * 4);
            ws[kq * 4 + 0][row] = w.x; ws[kq * 4 + 1][row] = w.y;
            ws[kq * 4 + 2][row] = w.z; ws[kq * 4 + 3][row] = w.w;
        }
        __syncthreads();
#pragma unroll 8
        for (int k = 0; k < 64; ++k) {
            float4 a = *(const float4*)&xs[k][r0];
            float4 b = *(const float4*)&ws[k][c0];
            acc[0][0] += a.x * b.x; acc[0][1] += a.x * b.y; acc[0][2] += a.x * b.z; acc[0][3] += a.x * b.w;
            acc[1][0] += a.y * b.x; acc[1][1] += a.y * b.y; acc[1][2] += a.y * b.z; acc[1][3] += a.y * b.w;
            acc[2][0] += a.z * b.x; acc[2][1] += a.z * b.y; acc[2][2] += a.z * b.z; acc[2][3] += a.z * b.w;
            acc[3][0] += a.w * b.x; acc[3][1] += a.w * b.y; acc[3][2] += a.w * b.z; acc[3][3] += a.w * b.w;
        }
        __syncthreads();
    }

    float4 bb = *(const float4*)(bih + bn * 64 + c0);
#pragma unroll
    for (int i = 0; i < 4; ++i) {
        float4 o;
        o.x = acc[i][0] + bb.x; o.y = acc[i][1] + bb.y;
        o.z = acc[i][2] + bb.z; o.w = acc[i][3] + bb.w;
        *(float4*)(g_xg + (size_t)(bm * 64 + r0 + i) * GG + bn * 64 + c0) = o;
    }
}

// ---------------------------------------------------------------------------
// Phase 2: persistent recurrent kernel.
// grid = 128 CTAs as 32 clusters of 4.
//   cluster id  (blockIdx.x>>2)  -> batch group g   (8 batch elements)
//   cluster rank                 -> hidden slice s  (64 hidden units, 192 gate rows)
// Each CTA caches its W_hh slice (k-major, fp32) in SMEM; per step it computes
// hg = h @ Wslice^T from a full local copy of h (assembled via DSMEM pushes),
// applies GRU gates, writes out[b][t][slice], pushes h_new to all 4 cluster
// CTAs, then cluster-syncs. Double-buffered h => one cluster sync per step.
// ---------------------------------------------------------------------------
#define TPB2   192
#define WPAD   196      // padded row width of wsm (floats)
// smem (floats): wsm 256*196 | hsm 2*256*8 | ps 192*8 | bsm 192
#define SM2_FLOATS (256 * WPAD + 2 * 256 * 8 + 192 * 8 + 192)
#define SM2_BYTES  (SM2_FLOATS * 4)

__device__ __forceinline__ void cluster_sync_() {
    asm volatile("barrier.cluster.arrive.aligned;" ::: "memory");
    asm volatile("barrier.cluster.wait.aligned;" ::: "memory");
}

__device__ __forceinline__ void push_cluster(uint32_t laddr, float v) {
#pragma unroll
    for (int r = 0; r < 4; ++r) {
        uint32_t ra;
        asm volatile("mapa.shared::cluster.u32 %0, %1, %2;" : "=r"(ra) : "r"(laddr), "r"(r));
        asm volatile("st.shared::cluster.f32 [%0], %1;" :: "r"(ra), "f"(v) : "memory");
    }
}

__global__ __launch_bounds__(TPB2, 1) __cluster_dims__(4, 1, 1)
void gru_seq_kernel(const float* __restrict__ Whh,
                    const float* __restrict__ bhh,
                    float* __restrict__ out)
{
    extern __shared__ float smf[];
    float* wsm = smf;                       // [256][WPAD]  W slice, k-major
    float* hsm = wsm + 256 * WPAD;          // [2][256][8]  full h, k-major, dbl buf
    float* ps  = hsm + 2 * 256 * 8;         // [192][8]     gate pre-activations
    float* bsm = ps + 192 * 8;              // [192]        b_hh slice

    const int tid = threadIdx.x;
    uint32_t srank;
    asm("mov.u32 %0, %%cluster_ctarank;" : "=r"(srank));
    const int s = (int)srank;               // hidden slice 0..3
    const int g = blockIdx.x >> 2;          // batch group 0..31

    // --- load W_hh slice transposed to k-major: wsm[k][r3] = Whh[grow(r3)][k]
    for (int i = tid; i < 192 * 256; i += TPB2) {
        int r3 = i >> 8;
        int k  = i & 255;
        int grow = ((r3 >> 6) << 8) + (s << 6) + (r3 & 63);   // gate*256 + s*64 + j
        wsm[k * WPAD + r3] = Whh[(size_t)grow * 256 + k];
    }
    if (tid < 192) {
        int grow = ((tid >> 6) << 8) + (s << 6) + (tid & 63);
        bsm[tid] = bhh[grow];
    }
    for (int i = tid; i < 2 * 256 * 8; i += TPB2) hsm[i] = 0.f;  // h0 = 0
    __syncthreads();
    cluster_sync_();

    // GEMM thread mapping: 192 threads = 2 k-halves x 2 batch-quads x 48 row-quads
    const int kk  = tid / 96;               // k half: [kk*128, kk*128+128)
    const int pos = tid % 96;
    const int b0  = (pos / 48) * 4;         // batch quad 0 or 4
    const int r0  = (pos % 48) * 4;         // gate rows r0..r0+3
    const float* wp = wsm + (size_t)kk * 128 * WPAD + r0;

    for (int t = 0; t < TT; ++t) {
        const int p = t & 1;
        const float* hb = hsm + p * 2048;
        const float* hp = hb + kk * 128 * 8 + b0;

        float a00 = 0.f, a01 = 0.f, a02 = 0.f, a03 = 0.f;
        float a10 = 0.f, a11 = 0.f, a12 = 0.f, a13 = 0.f;
        float a20 = 0.f, a21 = 0.f, a22 = 0.f, a23 = 0.f;
        float a30 = 0.f, a31 = 0.f, a32 = 0.f, a33 = 0.f;
#pragma unroll 4
        for (int k = 0; k < 128; ++k) {
            float4 hv = *(const float4*)(hp + (size_t)k * 8);
            float4 wv = *(const float4*)(wp + (size_t)k * WPAD);
            a00 += hv.x * wv.x; a01 += hv.x * wv.y; a02 += hv.x * wv.z; a03 += hv.x * wv.w;
            a10 += hv.y * wv.x; a11 += hv.y * wv.y; a12 += hv.y * wv.z; a13 += hv.y * wv.w;
            a20 += hv.z * wv.x; a21 += hv.z * wv.y; a22 += hv.z * wv.z; a23 += hv.z * wv.w;
            a30 += hv.w * wv.x; a31 += hv.w * wv.y; a32 += hv.w * wv.z; a33 += hv.w * wv.w;
        }
        if (kk) {   // k-half 1 deposits partials
            ps[(r0 + 0) * 8 + b0 + 0] = a00; ps[(r0 + 1) * 8 + b0 + 0] = a01;
            ps[(r0 + 2) * 8 + b0 + 0] = a02; ps[(r0 + 3) * 8 + b0 + 0] = a03;
            ps[(r0 + 0) * 8 + b0 + 1] = a10; ps[(r0 + 1) * 8 + b0 + 1] = a11;
            ps[(r0 + 2) * 8 + b0 + 1] = a12; ps[(r0 + 3) * 8 + b0 + 1] = a13;
            ps[(r0 + 0) * 8 + b0 + 2] = a20; ps[(r0 + 1) * 8 + b0 + 2] = a21;
            ps[(r0 + 2) * 8 + b0 + 2] = a22; ps[(r0 + 3) * 8 + b0 + 2] = a23;
            ps[(r0 + 0) * 8 + b0 + 3] = a30; ps[(r0 + 1) * 8 + b0 + 3] = a31;
            ps[(r0 + 2) * 8 + b0 + 3] = a32; ps[(r0 + 3) * 8 + b0 + 3] = a33;
        }
        __syncthreads();
        if (!kk) {  // k-half 0 reduces + adds b_hh
            float bz0 = bsm[r0 + 0], bz1 = bsm[r0 + 1], bz2 = bsm[r0 + 2], bz3 = bsm[r0 + 3];
            ps[(r0 + 0) * 8 + b0 + 0] += a00 + bz0; ps[(r0 + 1) * 8 + b0 + 0] += a01 + bz1;
            ps[(r0 + 2) * 8 + b0 + 0] += a02 + bz2; ps[(r0 + 3) * 8 + b0 + 0] += a03 + bz3;
            ps[(r0 + 0) * 8 + b0 + 1] += a10 + bz0; ps[(r0 + 1) * 8 + b0 + 1] += a11 + bz1;
            ps[(r0 + 2) * 8 + b0 + 1] += a12 + bz2; ps[(r0 + 3) * 8 + b0 + 1] += a13 + bz3;
            ps[(r0 + 0) * 8 + b0 + 2] += a20 + bz0; ps[(r0 + 1) * 8 + b0 + 2] += a21 + bz1;
            ps[(r0 + 2) * 8 + b0 + 2] += a22 + bz2; ps[(r0 + 3) * 8 + b0 + 2] += a23 + bz3;
            ps[(r0 + 0) * 8 + b0 + 3] += a30 + bz0; ps[(r0 + 1) * 8 + b0 + 3] += a31 + bz1;
            ps[(r0 + 2) * 8 + b0 + 3] += a32 + bz2; ps[(r0 + 3) * 8 + b0 + 3] += a33 + bz3;
        }
        __syncthreads();

        // --- gates + state update: 512 (b, j) outputs
        for (int idx = tid; idx < 512; idx += TPB2) {
            int b = idx >> 6;
            int j = idx & 63;
            float hr = ps[j * 8 + b];
            float hz = ps[(64 + j) * 8 + b];
            float hn = ps[(128 + j) * 8 + b];
            size_t xb = ((size_t)(g * 8 + b) * TT + t) * GG + (s << 6) + j;
            float xr = g_xg[xb];
            float xz = g_xg[xb + 256];
            float xn = g_xg[xb + 512];
            float r = __fdividef(1.f, 1.f + __expf(-(xr + hr)));
            float z = __fdividef(1.f, 1.f + __expf(-(xz + hz)));
            float v = xn + r * hn;
            float n = 1.f - 2.f * __fdividef(1.f, __expf(2.f * v) + 1.f);  // tanh(v)
            float hold = hb[((s << 6) + j) * 8 + b];
            float hnew = (1.f - z) * n + z * hold;
            out[((size_t)(g * 8 + b) * TT + t) * HH + (s << 6) + j] = hnew;
            uint32_t la = (uint32_t)__cvta_generic_to_shared(
                &hsm[(1 - p) * 2048 + ((s << 6) + j) * 8 + b]);
            push_cluster(la, hnew);
        }
        cluster_sync_();   // all pushes visible cluster-wide before next step
    }
}

// ---------------------------------------------------------------------------
// Launch
// ---------------------------------------------------------------------------
extern "C" void kernel_launch(void* const* d_in, const int* in_sizes, int n_in,
                              void* d_out, int out_size)
{
    const float* x   = (const float*)d_in[0];
    const float* Wih = (const float*)d_in[1];
    const float* Whh = (const float*)d_in[2];
    const float* bih = (const float*)d_in[3];
    const float* bhh = (const float*)d_in[4];
    float* out = (float*)d_out;

    cudaFuncSetAttribute(gru_seq_kernel,
                         cudaFuncAttributeMaxDynamicSharedMemorySize, SM2_BYTES);

    dim3 g1(BB * TT / 64, GG / 64);
    xg_gemm_kernel<<<g1, 256>>>(x, Wih, bih);
    gru_seq_kernel<<<128, TPB2, SM2_BYTES>>>(Whh, bhh, out);
}

// round 2
// speedup vs baseline: 1.7613x; 1.7613x over previous
#include <cuda_runtime.h>
#include <cstdint>
#include <cstddef>

#define BB 256
#define TT 512
#define II 128
#define HH 256
#define GG 768

__device__ float g_xg[(size_t)BB * TT * GG];

// ---------------- f32x2 helpers (sm_100+ packed fp32) ----------------
__device__ __forceinline__ unsigned long long pk2(float x, float y) {
    unsigned long long r;
    asm("mov.b64 %0, {%1, %2};" : "=l"(r) : "f"(x), "f"(y));
    return r;
}
__device__ __forceinline__ void up2(unsigned long long v, float& a, float& b) {
    asm("mov.b64 {%0, %1}, %2;" : "=f"(a), "=f"(b) : "l"(v));
}
__device__ __forceinline__ void fma2(unsigned long long& d,
                                     unsigned long long a, unsigned long long b) {
    asm("fma.rn.f32x2 %0, %1, %2, %0;" : "+l"(d) : "l"(a), "l"(b));
}
__device__ __forceinline__ unsigned long long add2(unsigned long long a,
                                                   unsigned long long b) {
    unsigned long long r;
    asm("add.rn.f32x2 %0, %1, %2;" : "=l"(r) : "l"(a), "l"(b));
    return r;
}
__device__ __forceinline__ void lds_v2b64(uint32_t addr,
                                          unsigned long long& a, unsigned long long& b) {
    asm volatile("ld.shared.v2.b64 {%0, %1}, [%2];" : "=l"(a), "=l"(b) : "r"(addr));
}
__device__ __forceinline__ void sts_v2b64(uint32_t addr,
                                          unsigned long long a, unsigned long long b) {
    asm volatile("st.shared.v2.b64 [%0], {%1, %2};" :: "r"(addr), "l"(a), "l"(b) : "memory");
}

// ---------------------------------------------------------------------------
// Phase 1:  xg = x @ W_ih^T + b_ih   (M=131072, N=768, K=128), FFMA2 inner loop
// ---------------------------------------------------------------------------
__global__ __launch_bounds__(256) void xg_gemm_kernel(
    const float* __restrict__ x,
    const float* __restrict__ Wih,
    const float* __restrict__ bih)
{
    __shared__ float xs[64][68];
    __shared__ float ws[64][68];
    const int tid = threadIdx.x;
    const int bm = blockIdx.x;
    const int bn = blockIdx.y;
    const float* xr = x   + (size_t)bm * 64 * II;
    const float* wr = Wih + (size_t)bn * 64 * II;
    const int r0 = (tid >> 4) << 2;
    const int c0 = (tid & 15) << 2;
    const uint32_t ws_s = (uint32_t)__cvta_generic_to_shared(&ws[0][0]);

    unsigned long long acc[4][2];
#pragma unroll
    for (int i = 0; i < 4; ++i) { acc[i][0] = 0ULL; acc[i][1] = 0ULL; }

    for (int kt = 0; kt < 2; ++kt) {
#pragma unroll
        for (int l = 0; l < 4; ++l) {
            int f   = l * 256 + tid;
            int row = f >> 4;
            int kq  = f & 15;
            float4 v = *(const float4*)(xr + (size_t)row * II + kt * 64 + kq * 4);
            xs[kq * 4 + 0][row] = v.x; xs[kq * 4 + 1][row] = v.y;
            xs[kq * 4 + 2][row] = v.z; xs[kq * 4 + 3][row] = v.w;
            float4 w = *(const float4*)(wr + (size_t)row * II + kt * 64 + kq * 4);
            ws[kq * 4 + 0][row] = w.x; ws[kq * 4 + 1][row] = w.y;
            ws[kq * 4 + 2][row] = w.z; ws[kq * 4 + 3][row] = w.w;
        }
        __syncthreads();
#pragma unroll 8
        for (int k = 0; k < 64; ++k) {
            float4 a = *(const float4*)&xs[k][r0];
            unsigned long long b01, b23;
            lds_v2b64(ws_s + (uint32_t)(k * 68 + c0) * 4u, b01, b23);
            unsigned long long a0 = pk2(a.x, a.x);
            unsigned long long a1 = pk2(a.y, a.y);
            unsigned long long a2 = pk2(a.z, a.z);
            unsigned long long a3 = pk2(a.w, a.w);
            fma2(acc[0][0], a0, b01); fma2(acc[0][1], a0, b23);
            fma2(acc[1][0], a1, b01); fma2(acc[1][1], a1, b23);
            fma2(acc[2][0], a2, b01); fma2(acc[2][1], a2, b23);
            fma2(acc[3][0], a3, b01); fma2(acc[3][1], a3, b23);
        }
        __syncthreads();
    }

    float4 bb = *(const float4*)(bih + bn * 64 + c0);
#pragma unroll
    for (int i = 0; i < 4; ++i) {
        float4 o;
        up2(acc[i][0], o.x, o.y);
        up2(acc[i][1], o.z, o.w);
        o.x += bb.x; o.y += bb.y; o.z += bb.z; o.w += bb.w;
        *(float4*)(g_xg + (size_t)(bm * 64 + r0 + i) * GG + bn * 64 + c0) = o;
    }
}

// ---------------------------------------------------------------------------
// Phase 2: persistent recurrent kernel. 32 clusters x 4 CTAs.
//   cluster -> 8 batches ; rank -> 64 hidden units (192 gate rows).
// 384 threads = 4 k-quarters x 96 row-pairs; each thread: rows (r, r+96),
// 8 batches as 4 f32x2 accumulators per row, 64 k-iters. FFMA2 GEMM.
// ---------------------------------------------------------------------------
#define TPB2 384
// floats: wsm 256*192 | hsm 2*256*8 | ps 3*192*8 | bsm 192
#define SM2_FLOATS (256 * 192 + 2 * 256 * 8 + 3 * 192 * 8 + 192)
#define SM2_BYTES  (SM2_FLOATS * 4)

__device__ __forceinline__ void cluster_sync_() {
    asm volatile("barrier.cluster.arrive.aligned;" ::: "memory");
    asm volatile("barrier.cluster.wait.aligned;" ::: "memory");
}

__global__ __launch_bounds__(TPB2, 1) __cluster_dims__(4, 1, 1)
void gru_seq_kernel(const float* __restrict__ Whh,
                    const float* __restrict__ bhh,
                    float* __restrict__ out)
{
    extern __shared__ float smf[];
    float* wsm = smf;                       // [256][192]  k-major weight slice
    float* hsm = wsm + 256 * 192;           // [2][256][8] full h, dbl buffered
    float* ps  = hsm + 2 * 256 * 8;         // [3][192][8] partials / final hg
    float* bsm = ps + 3 * 192 * 8;          // [192]

    const int tid = threadIdx.x;
    uint32_t srank;
    asm("mov.u32 %0, %%cluster_ctarank;" : "=r"(srank));
    const int s = (int)srank;
    const int g = blockIdx.x >> 2;

    const uint32_t hsm_s = (uint32_t)__cvta_generic_to_shared(hsm);
    const uint32_t ps_s  = (uint32_t)__cvta_generic_to_shared(ps);

    // load W slice: wsm[k*192 + r3] = Whh[grow(r3)][k]  (coalesced global reads)
    for (int i = tid; i < 192 * 256; i += TPB2) {
        int r3 = i >> 8;
        int k  = i & 255;
        int grow = ((r3 >> 6) << 8) + (s << 6) + (r3 & 63);
        wsm[k * 192 + r3] = Whh[(size_t)grow * 256 + k];
    }
    if (tid < 192) {
        int grow = ((tid >> 6) << 8) + (s << 6) + (tid & 63);
        bsm[tid] = bhh[grow];
    }
    for (int i = tid; i < 2 * 256 * 8; i += TPB2) hsm[i] = 0.f;
    __syncthreads();
    cluster_sync_();

    const int kq = tid / 96;            // k-quarter 0..3
    const int rp = tid % 96;            // row pair base (rows rp, rp+96)
    const int kbase = kq * 64;
    const int jj = tid >> 1;            // gate thread j (tid<128)
    const int bq = (tid & 1) * 4;       // gate batch quad

    for (int t = 0; t < TT; ++t) {
        const int p = t & 1;
        const float* hb = hsm + p * 2048;

        // prefetch xg for this step (hidden under the GEMM)
        float pxr[4], pxz[4], pxn[4];
        if (tid < 128) {
#pragma unroll
            for (int i = 0; i < 4; ++i) {
                size_t base = ((size_t)(g * 8 + bq + i) * TT + t) * GG + (s << 6) + jj;
                pxr[i] = g_xg[base];
                pxz[i] = g_xg[base + 256];
                pxn[i] = g_xg[base + 512];
            }
        }

        // ---- GEMM: hg[rows rp, rp+96][8 batches] over k-quarter ----
        unsigned long long a0q0 = 0, a0q1 = 0, a0q2 = 0, a0q3 = 0;
        unsigned long long a1q0 = 0, a1q1 = 0, a1q2 = 0, a1q3 = 0;
        {
            const float* wk = wsm + kbase * 192 + rp;
            uint32_t ha = hsm_s + (uint32_t)(p * 2048 + kbase * 8) * 4u;
#pragma unroll 4
            for (int k = 0; k < 64; ++k) {
                float w0 = wk[k * 192];
                float w1 = wk[k * 192 + 96];
                unsigned long long h01, h23, h45, h67;
                lds_v2b64(ha, h01, h23);
                lds_v2b64(ha + 16u, h45, h67);
                ha += 32u;
                unsigned long long w0d = pk2(w0, w0);
                unsigned long long w1d = pk2(w1, w1);
                fma2(a0q0, h01, w0d); fma2(a0q1, h23, w0d);
                fma2(a0q2, h45, w0d); fma2(a0q3, h67, w0d);
                fma2(a1q0, h01, w1d); fma2(a1q1, h23, w1d);
                fma2(a1q2, h45, w1d); fma2(a1q3, h67, w1d);
            }
        }

        if (kq) {   // deposit partials
            uint32_t d0 = ps_s + (uint32_t)((kq - 1) * 1536 + rp * 8) * 4u;
            uint32_t d1 = ps_s + (uint32_t)((kq - 1) * 1536 + (rp + 96) * 8) * 4u;
            sts_v2b64(d0,       a0q0, a0q1);
            sts_v2b64(d0 + 16u, a0q2, a0q3);
            sts_v2b64(d1,       a1q0, a1q1);
            sts_v2b64(d1 + 16u, a1q2, a1q3);
        }
        __syncthreads();
        if (kq == 0) {  // reduce 4 partials + bias -> final hg in ps[0]
#pragma unroll
            for (int m = 0; m < 2; ++m) {
                int row = rp + m * 96;
                unsigned long long f0 = m ? a1q0 : a0q0;
                unsigned long long f1 = m ? a1q1 : a0q1;
                unsigned long long f2 = m ? a1q2 : a0q2;
                unsigned long long f3 = m ? a1q3 : a0q3;
#pragma unroll
                for (int buf = 0; buf < 3; ++buf) {
                    uint32_t a = ps_s + (uint32_t)(buf * 1536 + row * 8) * 4u;
                    unsigned long long p0, p1, p2, p3;
                    lds_v2b64(a,       p0, p1);
                    lds_v2b64(a + 16u, p2, p3);
                    f0 = add2(f0, p0); f1 = add2(f1, p1);
                    f2 = add2(f2, p2); f3 = add2(f3, p3);
                }
                float bv = bsm[row];
                unsigned long long bd = pk2(bv, bv);
                f0 = add2(f0, bd); f1 = add2(f1, bd);
                f2 = add2(f2, bd); f3 = add2(f3, bd);
                uint32_t d = ps_s + (uint32_t)(row * 8) * 4u;
                sts_v2b64(d,       f0, f1);
                sts_v2b64(d + 16u, f2, f3);
            }
        }
        __syncthreads();

        // ---- gates + state update: 128 threads x (1 j, 4 batches) ----
        if (tid < 128) {
            float4 hr4 = *(const float4*)(ps + jj * 8 + bq);
            float4 hz4 = *(const float4*)(ps + (64 + jj) * 8 + bq);
            float4 hn4 = *(const float4*)(ps + (128 + jj) * 8 + bq);
            float4 ho4 = *(const float4*)(hb + ((s << 6) + jj) * 8 + bq);
            float hr[4] = {hr4.x, hr4.y, hr4.z, hr4.w};
            float hz[4] = {hz4.x, hz4.y, hz4.z, hz4.w};
            float hn[4] = {hn4.x, hn4.y, hn4.z, hn4.w};
            float ho[4] = {ho4.x, ho4.y, ho4.z, ho4.w};
            float hnew[4];
#pragma unroll
            for (int i = 0; i < 4; ++i) {
                float r = __fdividef(1.f, 1.f + __expf(-(pxr[i] + hr[i])));
                float z = __fdividef(1.f, 1.f + __expf(-(pxz[i] + hz[i])));
                float v = pxn[i] + r * hn[i];
                float n = 1.f - 2.f * __fdividef(1.f, __expf(2.f * v) + 1.f);
                hnew[i] = (1.f - z) * n + z * ho[i];
                out[((size_t)(g * 8 + bq + i) * TT + t) * HH + (s << 6) + jj] = hnew[i];
            }
            uint32_t la = hsm_s + (uint32_t)((1 - p) * 2048 + ((s << 6) + jj) * 8 + bq) * 4u;
#pragma unroll
            for (int rk = 0; rk < 4; ++rk) {
                uint32_t ra;
                asm volatile("mapa.shared::cluster.u32 %0, %1, %2;"
                             : "=r"(ra) : "r"(la), "r"(rk));
                asm volatile("st.shared::cluster.v4.f32 [%0], {%1, %2, %3, %4};"
                             :: "r"(ra), "f"(hnew[0]), "f"(hnew[1]),
                                "f"(hnew[2]), "f"(hnew[3]) : "memory");
            }
        }
        cluster_sync_();
    }
}

// ---------------------------------------------------------------------------
extern "C" void kernel_launch(void* const* d_in, const int* in_sizes, int n_in,
                              void* d_out, int out_size)
{
    const float* x   = (const float*)d_in[0];
    const float* Wih = (const float*)d_in[1];
    const float* Whh = (const float*)d_in[2];
    const float* bih = (const float*)d_in[3];
    const float* bhh = (const float*)d_in[4];
    float* out = (float*)d_out;

    cudaFuncSetAttribute(gru_seq_kernel,
                         cudaFuncAttributeMaxDynamicSharedMemorySize, SM2_BYTES);

    dim3 g1(BB * TT / 64, GG / 64);
    xg_gemm_kernel<<<g1, 256>>>(x, Wih, bih);
    gru_seq_kernel<<<128, TPB2, SM2_BYTES>>>(Whh, bhh, out);
}